// round 3
// baseline (speedup 1.0000x reference)
#include <cuda_runtime.h>

typedef unsigned long long ull;

// ---------------- shared weight image (floats) ----------------
// NH row = 76 floats (38 pairs, matches v[38]):
//   [0..31] W_hh[j][*]   (v[0..15]=h)
//   [32..33] (b_ih+b_hh, 0)  (v[16]=(1,0))
//   [34..73] W_ih[j][0..39]  (v[17..36]=s,a)
//   [74..75] 0               (v[37]=(0,0))
// M row = 36 floats (9 pairs): [0..31]=w, [32..33]=(b,0), [34..35]=0
// 4 row-groups of 8 rows; each group skewed +4 floats so the 4 distinct
// LDS.128 addresses per warp land 4 banks apart (conflict-free).
#define NH_ROW 76
#define M_ROW  36
#define NH_GRP (8*NH_ROW + 4)                 // 612
#define M_GRP  (8*M_ROW + 4)                  // 292
#define NH_SZ  (4*NH_GRP)                     // 2448
#define M_SZ   (4*M_GRP)                      // 1168
#define FC1_OFF  NH_SZ                        // 2448
#define MEAN_OFF (FC1_OFF + M_SZ)             // 3616
#define STD_OFF  (MEAN_OFF + M_SZ)            // 4784
#define SMEM_FLOATS (STD_OFF + M_SZ)          // 5952 floats = 23808 B

union F4U { float4 f; ulonglong2 u; };

__device__ __forceinline__ ull pack2(float lo, float hi){
  ull r; asm("mov.b64 %0, {%1,%2};" : "=l"(r) : "f"(lo), "f"(hi)); return r;
}
__device__ __forceinline__ float2 unpack2(ull v){
  float2 r; asm("mov.b64 {%0,%1}, %2;" : "=f"(r.x), "=f"(r.y) : "l"(v)); return r;
}
__device__ __forceinline__ ull fma2(ull a, ull b, ull c){
  ull d; asm("fma.rn.f32x2 %0, %1, %2, %3;" : "=l"(d) : "l"(a), "l"(b), "l"(c)); return d;
}
__device__ __forceinline__ float hsum(ull a){ float2 f = unpack2(a); return f.x + f.y; }

__device__ __forceinline__ float tanh_approx(float x){
  float y; asm("tanh.approx.f32 %0, %1;" : "=f"(y) : "f"(x)); return y;
}
__device__ __forceinline__ float softplus_fast(float x){
  float e = __expf(-fabsf(x));
  return fmaxf(x, 0.0f) + __logf(1.0f + e);
}

// 8 simultaneous row-dots (my 8 rows) against packed vector v. RS = row
// stride in ulonglong2 units (19 for NH rows, 9 for M rows).
template<int NP, int RS>
__device__ __forceinline__ void dot8(const ulonglong2* __restrict__ base,
                                     const ull* v, float* o){
  ull acc[8];
#pragma unroll
  for (int r=0;r<8;r++) acc[r]=0ull;
#pragma unroll
  for (int p=0;p<NP;p++){
    ull vl=v[2*p], vh=v[2*p+1];
#pragma unroll
    for (int r=0;r<8;r++){
      ulonglong2 w = base[r*RS + p];
      acc[r]=fma2(w.x,vl,acc[r]);
      acc[r]=fma2(w.y,vh,acc[r]);
    }
  }
#pragma unroll
  for (int r=0;r<8;r++) o[r]=hsum(acc[r]);
}

// 4-lane butterfly: my 8 floats (rows rg*8..rg*8+7) -> dst[0..15] = full
// packed 32-value vector in row order. 12 SHFL, constant indices.
__device__ __forceinline__ void exchange8(const float* my, ull* dst, int rg){
  ull m[4];
#pragma unroll
  for (int i=0;i<4;i++) m[i]=pack2(my[2*i], my[2*i+1]);
  ull h8[8];
#pragma unroll
  for (int i=0;i<4;i++){
    ull o = __shfl_xor_sync(0xFFFFFFFFu, m[i], 1);
    h8[i]   = (rg&1) ? o : m[i];
    h8[4+i] = (rg&1) ? m[i] : o;
  }
#pragma unroll
  for (int i=0;i<8;i++){
    ull o = __shfl_xor_sync(0xFFFFFFFFu, h8[i], 2);
    dst[i]   = (rg&2) ? o : h8[i];
    dst[8+i] = (rg&2) ? h8[i] : o;
  }
}

__global__ void __launch_bounds__(128)
rssm_kernel(const float* __restrict__ s0, const float* __restrict__ h0,
            const float* __restrict__ actions,
            const float* __restrict__ W_ih, const float* __restrict__ W_hh,
            const float* __restrict__ b_ih, const float* __restrict__ b_hh,
            const float* __restrict__ fc1_w, const float* __restrict__ fc1_b,
            const float* __restrict__ mean_w, const float* __restrict__ mean_b,
            const float* __restrict__ std_w, const float* __restrict__ std_b,
            float* __restrict__ out, int B, int T, int n_steps)
{
  __shared__ __align__(16) float sw[SMEM_FLOATS];
  const int tid = threadIdx.x;

  // ---- stage weights (128 threads) ----
  for (int i=tid;i<SMEM_FLOATS;i+=128) sw[i]=0.0f;
  __syncthreads();
  for (int i=tid;i<32*32;i+=128){ int j=i>>5,k=i&31; sw[j*NH_ROW+((j>>3)<<2)+k]=W_hh[i]; }
  for (int i=tid;i<32*40;i+=128){ int j=i/40,k=i-j*40; sw[j*NH_ROW+((j>>3)<<2)+34+k]=W_ih[i]; }
  for (int i=tid;i<32*32;i+=128){
    int j=i>>5,k=i&31; int sk=((j>>3)<<2);
    sw[FC1_OFF + j*M_ROW+sk+k]=fc1_w[i];
    sw[MEAN_OFF+ j*M_ROW+sk+k]=mean_w[i];
    sw[STD_OFF + j*M_ROW+sk+k]=std_w[i];
  }
  if (tid < 32){
    int j=tid; int sk=((j>>3)<<2);
    sw[j*NH_ROW+sk+32]          = b_ih[j]+b_hh[j];
    sw[FC1_OFF + j*M_ROW+sk+32] = fc1_b[j];
    sw[MEAN_OFF+ j*M_ROW+sk+32] = mean_b[j];
    sw[STD_OFF + j*M_ROW+sk+32] = std_b[j];
  }
  __syncthreads();

  const int rg   = tid & 3;                       // my 8-row group
  const int elem = blockIdx.x*32 + (tid>>2);      // batch element

  const ulonglong2* nhb = (const ulonglong2*)(sw + rg*NH_GRP);
  const ulonglong2* f1b = (const ulonglong2*)(sw + FC1_OFF  + rg*M_GRP);
  const ulonglong2* mnb = (const ulonglong2*)(sw + MEAN_OFF + rg*M_GRP);
  const ulonglong2* sdb = (const ulonglong2*)(sw + STD_OFF  + rg*M_GRP);

  // v = [h(16 pairs), ONE, s(16 pairs), a(4 pairs), ZERO]; u = [hid(16), ONE, ZERO]
  ull v[38];
  ull u[18];
  {
    const float4* h4 = (const float4*)(h0 + (size_t)elem*32);
    const float4* s4 = (const float4*)(s0 + (size_t)elem*32);
#pragma unroll
    for (int q=0;q<8;q++){
      F4U th; th.f=h4[q]; v[2*q]=th.u.x;    v[2*q+1]=th.u.y;
      F4U ts; ts.f=s4[q]; v[17+2*q]=ts.u.x; v[18+2*q]=ts.u.y;
    }
    v[16]=pack2(1.0f,0.0f);
    v[37]=0ull;
    u[16]=pack2(1.0f,0.0f);
    u[17]=0ull;
    const float4* a4=(const float4*)(actions + (size_t)elem*T*8);
    F4U a0; a0.f=a4[0]; F4U a1; a1.f=a4[1];
    v[33]=a0.u.x; v[34]=a0.u.y; v[35]=a1.u.x; v[36]=a1.u.y;
  }

  for (int t=0;t<n_steps;t++){
    // prefetch next step's action
    F4U an0, an1; an0.u.x=0ull; an0.u.y=0ull; an1.u.x=0ull; an1.u.y=0ull;
    if (t+1<n_steps){
      const float4* a4=(const float4*)(actions + ((size_t)elem*T + t+1)*8);
      an0.f=a4[0]; an1.f=a4[1];
    }

    // ---- h_t = tanh(W_ih @ [s,a] + b + W_hh @ h) ----
    float myh[8];
    dot8<19,19>(nhb, v, myh);
#pragma unroll
    for (int i=0;i<8;i++) myh[i]=tanh_approx(myh[i]);
    exchange8(myh, v, rg);                        // v[0..15] = new h

    // ---- hid = elu(fc1 @ h + b) ----
    float myhid[8];
    dot8<9,9>(f1b, v, myhid);
#pragma unroll
    for (int i=0;i<8;i++){ float x=myhid[i]; myhid[i]= x>0.0f ? x : (__expf(x)-1.0f); }
    exchange8(myhid, u, rg);                      // u[0..15] = hid

    // ---- mean = mean_w @ hid + b (also next-step s) ----
    float mym[8];
    dot8<9,9>(mnb, u, mym);

    float* orow = out + ((size_t)t*B + elem)*64 + rg*8;
    {
      float4 f0; f0.x=mym[0]; f0.y=mym[1]; f0.z=mym[2]; f0.w=mym[3];
      float4 f1; f1.x=mym[4]; f1.y=mym[5]; f1.z=mym[6]; f1.w=mym[7];
      ((float4*)orow)[0]=f0; ((float4*)orow)[1]=f1;
    }
    exchange8(mym, v+17, rg);                     // v[17..32] = new s

    // ---- stddev = softplus(std_w @ hid + b) + 1e-5 ----
    float mys[8];
    dot8<9,9>(sdb, u, mys);
#pragma unroll
    for (int i=0;i<8;i++) mys[i]=softplus_fast(mys[i])+1e-5f;
    {
      float4 f0; f0.x=mys[0]; f0.y=mys[1]; f0.z=mys[2]; f0.w=mys[3];
      float4 f1; f1.x=mys[4]; f1.y=mys[5]; f1.z=mys[6]; f1.w=mys[7];
      ((float4*)(orow+32))[0]=f0; ((float4*)(orow+32))[1]=f1;
    }

    // commit prefetched action
    v[33]=an0.u.x; v[34]=an0.u.y; v[35]=an1.u.x; v[36]=an1.u.y;
  }
}

extern "C" void kernel_launch(void* const* d_in, const int* in_sizes, int n_in,
                              void* d_out, int out_size) {
  const float* s0      = (const float*)d_in[0];
  const float* h0      = (const float*)d_in[1];
  const float* actions = (const float*)d_in[2];
  const float* W_ih    = (const float*)d_in[3];
  const float* W_hh    = (const float*)d_in[4];
  const float* b_ih    = (const float*)d_in[5];
  const float* b_hh    = (const float*)d_in[6];
  const float* fc1_w   = (const float*)d_in[7];
  const float* fc1_b   = (const float*)d_in[8];
  const float* mean_w  = (const float*)d_in[9];
  const float* mean_b  = (const float*)d_in[10];
  const float* std_w   = (const float*)d_in[11];
  const float* std_b   = (const float*)d_in[12];
  float* out = (float*)d_out;

  int B = in_sizes[0] / 32;                 // s0 is [B, 32]
  int T = in_sizes[2] / (B * 8);            // actions is [B, T, 8]
  int n_steps = out_size / (B * 64);        // out is [n_steps, B, 64]
  if (n_steps > T) n_steps = T;

  cudaFuncSetAttribute(rssm_kernel, cudaFuncAttributePreferredSharedMemoryCarveout, 100);

  rssm_kernel<<<B/32, 128>>>(s0, h0, actions, W_ih, W_hh, b_ih, b_hh,
                             fc1_w, fc1_b, mean_w, mean_b, std_w, std_b,
                             out, B, T, n_steps);
}

// round 4
// speedup vs baseline: 1.4592x; 1.4592x over previous
#include <cuda_runtime.h>

typedef unsigned long long ull;

// ---------------- shared weight image (floats, no skew: reads are warp-uniform) ----
// NH row j (76 floats = 19 x 16B): [0..31]=W_hh[j], [32..33]=(b_ih[j]+b_hh[j],0),
//                                  [34..73]=W_ih[j][0..39], [74..75]=0
//   consumed against v[38] = [h(16 ull), ONE, s(16), a(4), ZERO]
// M row j (36 floats = 9 x 16B): [0..31]=w[j], [32..33]=(b[j],0), [34..35]=0
//   consumed against u[18] = [x(16 ull), ONE, ZERO]
#define NH_ROW 76
#define M_ROW  36
#define FC1_OFF  (32*NH_ROW)              // 2432
#define MEAN_OFF (FC1_OFF + 32*M_ROW)     // 3584
#define STD_OFF  (MEAN_OFF + 32*M_ROW)    // 4736
#define W_FLOATS (STD_OFF + 32*M_ROW)     // 5888 floats = 23552 B (16B aligned)

// exchange buffer: 3 slots x 32 elems x 18 ull (16 used + 2 pad -> lane stride
// 144B = 9 x 16B, odd -> conflict-free STS.128/LDS.128 phases)
#define BUF_STRIDE 18
#define BUF_SLOT   (32*BUF_STRIDE)        // 576 ull
#define BUF_ULL    (3*BUF_SLOT)           // 1728 ull = 13824 B
#define SLOT_H    0
#define SLOT_HID  1
#define SLOT_S    2

union F4U { float4 f; ulonglong2 u; };

__device__ __forceinline__ ull pack2(float lo, float hi){
  ull r; asm("mov.b64 %0, {%1,%2};" : "=l"(r) : "f"(lo), "f"(hi)); return r;
}
__device__ __forceinline__ float2 unpack2(ull v){
  float2 r; asm("mov.b64 {%0,%1}, %2;" : "=f"(r.x), "=f"(r.y) : "l"(v)); return r;
}
__device__ __forceinline__ ull fma2(ull a, ull b, ull c){
  ull d; asm("fma.rn.f32x2 %0, %1, %2, %3;" : "=l"(d) : "l"(a), "l"(b), "l"(c)); return d;
}
__device__ __forceinline__ float hsum(ull a){ float2 f = unpack2(a); return f.x + f.y; }

__device__ __forceinline__ float tanh_approx(float x){
  float y; asm("tanh.approx.f32 %0, %1;" : "=f"(y) : "f"(x)); return y;
}
__device__ __forceinline__ float softplus_fast(float x){
  float e = __expf(-fabsf(x));
  return fmaxf(x, 0.0f) + __logf(1.0f + e);
}

// 8 row-dots for my warp's row block. Weight addresses are WARP-UNIFORM
// (all lanes read the same row) -> 1 distinct address per LDS.128.
template<int NP>
__device__ __forceinline__ void dot8u(const float* __restrict__ wbase, int rowstride_f,
                                      const ull* v, float* y){
#pragma unroll
  for (int r=0;r<8;r++){
    const ulonglong2* row = (const ulonglong2*)(wbase + r*rowstride_f);
    ull acc = 0ull;
#pragma unroll
    for (int p=0;p<NP;p++){
      ulonglong2 w = row[p];                 // uniform LDS.128
      acc = fma2(w.x, v[2*p],   acc);
      acc = fma2(w.y, v[2*p+1], acc);
    }
    y[r] = hsum(acc);
  }
}

// write my 8 values (rows 8w..8w+7) packed into exchange slot
__device__ __forceinline__ void put8(ull* buf, int slot, int lane, int w, const float* y){
  ulonglong2* dst = (ulonglong2*)(buf + slot*BUF_SLOT + lane*BUF_STRIDE + w*4);
  ulonglong2 q0, q1;
  q0.x = pack2(y[0],y[1]); q0.y = pack2(y[2],y[3]);
  q1.x = pack2(y[4],y[5]); q1.y = pack2(y[6],y[7]);
  dst[0]=q0; dst[1]=q1;                      // 2 STS.128, conflict-free
}

// read full 32-value packed vector (16 ull) for my element
__device__ __forceinline__ void get16(const ull* buf, int slot, int lane, ull* dst){
  const ulonglong2* src = (const ulonglong2*)(buf + slot*BUF_SLOT + lane*BUF_STRIDE);
#pragma unroll
  for (int q=0;q<8;q++){ ulonglong2 v = src[q]; dst[2*q]=v.x; dst[2*q+1]=v.y; }
}

__global__ void __launch_bounds__(128)
rssm_kernel(const float* __restrict__ s0, const float* __restrict__ h0,
            const float* __restrict__ actions,
            const float* __restrict__ W_ih, const float* __restrict__ W_hh,
            const float* __restrict__ b_ih, const float* __restrict__ b_hh,
            const float* __restrict__ fc1_w, const float* __restrict__ fc1_b,
            const float* __restrict__ mean_w, const float* __restrict__ mean_b,
            const float* __restrict__ std_w, const float* __restrict__ std_b,
            float* __restrict__ out, int B, int T, int n_steps)
{
  __shared__ __align__(16) float sw[W_FLOATS];
  __shared__ __align__(16) ull  xbuf[BUF_ULL];
  const int tid  = threadIdx.x;
  const int w    = tid >> 5;                 // warp id 0..3 -> rows 8w..8w+7
  const int lane = tid & 31;                 // batch element within group
  const int elem = blockIdx.x*32 + lane;

  // ---- stage weights (plain layout) ----
  for (int i=tid;i<W_FLOATS;i+=128) sw[i]=0.0f;
  __syncthreads();
  for (int i=tid;i<32*32;i+=128){ int j=i>>5,k=i&31; sw[j*NH_ROW+k]=W_hh[i]; }
  for (int i=tid;i<32*40;i+=128){ int j=i/40,k=i-j*40; sw[j*NH_ROW+34+k]=W_ih[i]; }
  for (int i=tid;i<32*32;i+=128){
    int j=i>>5,k=i&31;
    sw[FC1_OFF + j*M_ROW+k]=fc1_w[i];
    sw[MEAN_OFF+ j*M_ROW+k]=mean_w[i];
    sw[STD_OFF + j*M_ROW+k]=std_w[i];
  }
  if (tid < 32){
    int j=tid;
    sw[j*NH_ROW+32]          = b_ih[j]+b_hh[j];
    sw[FC1_OFF + j*M_ROW+32] = fc1_b[j];
    sw[MEAN_OFF+ j*M_ROW+32] = mean_b[j];
    sw[STD_OFF + j*M_ROW+32] = std_b[j];
  }

  // seed SLOT_S with s0 (warp 0 only)
  if (w == 0){
    const float4* s4 = (const float4*)(s0 + (size_t)elem*32);
    ulonglong2* dst = (ulonglong2*)(xbuf + SLOT_S*BUF_SLOT + lane*BUF_STRIDE);
#pragma unroll
    for (int q=0;q<8;q++){ F4U t; t.f=s4[q]; ulonglong2 v; v.x=t.u.x; v.y=t.u.y; dst[q]=v; }
  }
  __syncthreads();

  const float* nhb = sw + (w*8)*NH_ROW;
  const float* f1b = sw + FC1_OFF  + (w*8)*M_ROW;
  const float* mnb = sw + MEAN_OFF + (w*8)*M_ROW;
  const float* sdb = sw + STD_OFF  + (w*8)*M_ROW;

  const ull ONE = pack2(1.0f, 0.0f);

  // h kept in registers (16 ull packed pairs), loaded from h0
  ull h[16];
  {
    const float4* h4 = (const float4*)(h0 + (size_t)elem*32);
#pragma unroll
    for (int q=0;q<8;q++){ F4U t; t.f=h4[q]; h[2*q]=t.u.x; h[2*q+1]=t.u.y; }
  }
  // first action
  ull a[4];
  {
    const float4* a4=(const float4*)(actions + (size_t)elem*T*8);
    F4U a0; a0.f=a4[0]; F4U a1; a1.f=a4[1];
    a[0]=a0.u.x; a[1]=a0.u.y; a[2]=a1.u.x; a[3]=a1.u.y;
  }

  for (int t=0;t<n_steps;t++){
    // prefetch next action (hide LDG latency behind this step)
    F4U an0, an1; an0.u.x=0ull; an0.u.y=0ull; an1.u.x=0ull; an1.u.y=0ull;
    if (t+1<n_steps){
      const float4* a4=(const float4*)(actions + ((size_t)elem*T + t+1)*8);
      an0.f=a4[0]; an1.f=a4[1];
    }

    // ---- build v = [h, ONE, s, a, ZERO]; s read from SLOT_S ----
    ull v[38];
#pragma unroll
    for (int i=0;i<16;i++) v[i]=h[i];
    v[16]=ONE;
    get16(xbuf, SLOT_S, lane, v+17);
    v[33]=a[0]; v[34]=a[1]; v[35]=a[2]; v[36]=a[3];
    v[37]=0ull;

    // ---- h_t rows 8w..8w+7 = tanh(NH @ v) ----
    float yh[8];
    dot8u<19>(nhb, NH_ROW, v, yh);
#pragma unroll
    for (int i=0;i<8;i++) yh[i]=tanh_approx(yh[i]);
    put8(xbuf, SLOT_H, lane, w, yh);
    __syncthreads();
    get16(xbuf, SLOT_H, lane, h);                 // full new h -> registers

    // ---- hid = elu(FC1 @ [h,1]) ----
    ull u[18];
#pragma unroll
    for (int i=0;i<16;i++) u[i]=h[i];
    u[16]=ONE; u[17]=0ull;
    float yf[8];
    dot8u<9>(f1b, M_ROW, u, yf);
#pragma unroll
    for (int i=0;i<8;i++){ float x=yf[i]; yf[i] = x>0.0f ? x : (__expf(x)-1.0f); }
    put8(xbuf, SLOT_HID, lane, w, yf);
    __syncthreads();
    get16(xbuf, SLOT_HID, lane, u);               // full hid
    u[16]=ONE; u[17]=0ull;

    // ---- mean rows = MEAN @ [hid,1]  (also next-step s) ----
    float ym[8];
    dot8u<9>(mnb, M_ROW, u, ym);
    put8(xbuf, SLOT_S, lane, w, ym);

    float* orow = out + ((size_t)t*B + elem)*64 + w*8;
    {
      float4 f0; f0.x=ym[0]; f0.y=ym[1]; f0.z=ym[2]; f0.w=ym[3];
      float4 f1; f1.x=ym[4]; f1.y=ym[5]; f1.z=ym[6]; f1.w=ym[7];
      ((float4*)orow)[0]=f0; ((float4*)orow)[1]=f1;
    }

    // ---- std rows = softplus(STD @ [hid,1]) + 1e-5 ----
    float ys[8];
    dot8u<9>(sdb, M_ROW, u, ys);
#pragma unroll
    for (int i=0;i<8;i++) ys[i]=softplus_fast(ys[i])+1e-5f;
    {
      float4 f0; f0.x=ys[0]; f0.y=ys[1]; f0.z=ys[2]; f0.w=ys[3];
      float4 f1; f1.x=ys[4]; f1.y=ys[5]; f1.z=ys[6]; f1.w=ys[7];
      ((float4*)(orow+32))[0]=f0; ((float4*)(orow+32))[1]=f1;
    }

    // commit prefetched action; make SLOT_S writes visible for next step's read
    a[0]=an0.u.x; a[1]=an0.u.y; a[2]=an1.u.x; a[3]=an1.u.y;
    __syncthreads();
  }
}

extern "C" void kernel_launch(void* const* d_in, const int* in_sizes, int n_in,
                              void* d_out, int out_size) {
  const float* s0      = (const float*)d_in[0];
  const float* h0      = (const float*)d_in[1];
  const float* actions = (const float*)d_in[2];
  const float* W_ih    = (const float*)d_in[3];
  const float* W_hh    = (const float*)d_in[4];
  const float* b_ih    = (const float*)d_in[5];
  const float* b_hh    = (const float*)d_in[6];
  const float* fc1_w   = (const float*)d_in[7];
  const float* fc1_b   = (const float*)d_in[8];
  const float* mean_w  = (const float*)d_in[9];
  const float* mean_b  = (const float*)d_in[10];
  const float* std_w   = (const float*)d_in[11];
  const float* std_b   = (const float*)d_in[12];
  float* out = (float*)d_out;

  int B = in_sizes[0] / 32;                 // s0 is [B, 32]
  int T = in_sizes[2] / (B * 8);            // actions is [B, T, 8]
  int n_steps = out_size / (B * 64);        // out is [n_steps, B, 64]
  if (n_steps > T) n_steps = T;

  cudaFuncSetAttribute(rssm_kernel, cudaFuncAttributePreferredSharedMemoryCarveout, 100);

  rssm_kernel<<<B/32, 128>>>(s0, h0, actions, W_ih, W_hh, b_ih, b_hh,
                             fc1_w, fc1_b, mean_w, mean_b, std_w, std_b,
                             out, B, T, n_steps);
}

// round 5
// speedup vs baseline: 1.8066x; 1.2381x over previous
#include <cuda_runtime.h>

typedef unsigned long long ull;

// ---------------- shared weight image (floats; reads are warp-uniform) ----------
// NH row j (76 floats = 19 x 16B): [0..31]=W_hh[j], [32..33]=(b_ih[j]+b_hh[j],0),
//                                  [34..73]=W_ih[j][0..39], [74..75]=0
// M row j  (36 floats =  9 x 16B): [0..31]=w[j],    [32..33]=(b[j],0), [34..35]=0
#define NH_ROW 76
#define M_ROW  36
#define FC1_OFF  (32*NH_ROW)              // 2432
#define MEAN_OFF (FC1_OFF + 32*M_ROW)     // 3584
#define STD_OFF  (MEAN_OFF + 32*M_ROW)    // 4736
#define W_FLOATS (STD_OFF + 32*M_ROW)     // 5888 floats = 23552 B

// exchange buffer: 3 slots x 64 elems x 18 ull (16 used + 2 pad).
// lane stride = 18 ull = 9 x 16B chunks; 9 mod 8 = 1 -> within each 8-lane
// phase of an LDS/STS.128 all 8 16B-chunks are distinct -> conflict-free.
#define BUF_STRIDE 18
#define BUF_SLOT   (64*BUF_STRIDE)        // 1152 ull
#define BUF_ULL    (3*BUF_SLOT)           // 3456 ull = 27648 B
#define SLOT_H    0
#define SLOT_HID  1
#define SLOT_S    2

union F4U { float4 f; ulonglong2 u; };

__device__ __forceinline__ ull pack2(float lo, float hi){
  ull r; asm("mov.b64 %0, {%1,%2};" : "=l"(r) : "f"(lo), "f"(hi)); return r;
}
__device__ __forceinline__ float2 unpack2(ull v){
  float2 r; asm("mov.b64 {%0,%1}, %2;" : "=f"(r.x), "=f"(r.y) : "l"(v)); return r;
}
__device__ __forceinline__ ull fma2(ull a, ull b, ull c){
  ull d; asm("fma.rn.f32x2 %0, %1, %2, %3;" : "=l"(d) : "l"(a), "l"(b), "l"(c)); return d;
}
__device__ __forceinline__ float hsum(ull a){ float2 f = unpack2(a); return f.x + f.y; }

__device__ __forceinline__ float tanh_approx(float x){
  float y; asm("tanh.approx.f32 %0, %1;" : "=f"(y) : "f"(x)); return y;
}
__device__ __forceinline__ float softplus_fast(float x){
  float e = __expf(-fabsf(x));
  return fmaxf(x, 0.0f) + __logf(1.0f + e);
}

// NH matvec, 8 rows, 2 elements. Weight reads warp-uniform; each LDS.128
// feeds 4 FMA2. Accumulators live only per-row (register pressure).
__device__ __forceinline__ void dotNH2(const float* __restrict__ wbase,
                                       const ull* hA, const ull* hB,
                                       const ull* sA, const ull* sB,
                                       const ull* aA, const ull* aB,
                                       ull ONE, float* yA, float* yB){
#pragma unroll
  for (int r=0;r<8;r++){
    const ulonglong2* row = (const ulonglong2*)(wbase + r*NH_ROW);
    ull accA=0ull, accB=0ull;
#pragma unroll
    for (int p=0;p<8;p++){                       // w_hh: 16 ull vs h[0..15]
      ulonglong2 w = row[p];
      accA=fma2(w.x,hA[2*p],accA); accB=fma2(w.x,hB[2*p],accB);
      accA=fma2(w.y,hA[2*p+1],accA); accB=fma2(w.y,hB[2*p+1],accB);
    }
    {                                            // bias pair + first w_ih ull
      ulonglong2 w = row[8];                     // w.x=(b,0), w.y=w_ih pair0
      accA=fma2(w.x,ONE,accA);       accB=fma2(w.x,ONE,accB);
      accA=fma2(w.y,sA[0],accA);     accB=fma2(w.y,sB[0],accB);
    }
#pragma unroll
    for (int p=0;p<7;p++){                       // w_ih pairs 1..14 (s)
      ulonglong2 w = row[9+p];
      accA=fma2(w.x,sA[1+2*p],accA); accB=fma2(w.x,sB[1+2*p],accB);
      accA=fma2(w.y,sA[2+2*p],accA); accB=fma2(w.y,sB[2+2*p],accB);
    }
    {                                            // s pair 15 + a pair 0
      ulonglong2 w = row[16];
      accA=fma2(w.x,sA[15],accA);    accB=fma2(w.x,sB[15],accB);
      accA=fma2(w.y,aA[0],accA);     accB=fma2(w.y,aB[0],accB);
    }
    {                                            // a pairs 1,2
      ulonglong2 w = row[17];
      accA=fma2(w.x,aA[1],accA);     accB=fma2(w.x,aB[1],accB);
      accA=fma2(w.y,aA[2],accA);     accB=fma2(w.y,aB[2],accB);
    }
    {                                            // a pair 3 (+ pad, skipped)
      ulonglong2 w = row[18];
      accA=fma2(w.x,aA[3],accA);     accB=fma2(w.x,aB[3],accB);
    }
    yA[r]=hsum(accA); yB[r]=hsum(accB);
  }
}

// M matvec (fc1/mean/std), 8 rows, 2 elements, x = 16 packed pairs + bias.
__device__ __forceinline__ void dotM2(const float* __restrict__ wbase,
                                      const ull* xA, const ull* xB,
                                      ull ONE, float* yA, float* yB){
#pragma unroll
  for (int r=0;r<8;r++){
    const ulonglong2* row = (const ulonglong2*)(wbase + r*M_ROW);
    ull accA=0ull, accB=0ull;
#pragma unroll
    for (int p=0;p<8;p++){
      ulonglong2 w = row[p];
      accA=fma2(w.x,xA[2*p],accA); accB=fma2(w.x,xB[2*p],accB);
      accA=fma2(w.y,xA[2*p+1],accA); accB=fma2(w.y,xB[2*p+1],accB);
    }
    {
      ulonglong2 w = row[8];                     // (bias,0) + zero pad
      accA=fma2(w.x,ONE,accA); accB=fma2(w.x,ONE,accB);
    }
    yA[r]=hsum(accA); yB[r]=hsum(accB);
  }
}

// write my 8 values for element e into exchange slot
__device__ __forceinline__ void put8(ull* buf, int slot, int e, int w, const float* y){
  ulonglong2* dst = (ulonglong2*)(buf + slot*BUF_SLOT + e*BUF_STRIDE + w*4);
  ulonglong2 q0, q1;
  q0.x = pack2(y[0],y[1]); q0.y = pack2(y[2],y[3]);
  q1.x = pack2(y[4],y[5]); q1.y = pack2(y[6],y[7]);
  dst[0]=q0; dst[1]=q1;
}

// read full 32-value packed vector (16 ull) for element e
__device__ __forceinline__ void get16(const ull* buf, int slot, int e, ull* dst){
  const ulonglong2* src = (const ulonglong2*)(buf + slot*BUF_SLOT + e*BUF_STRIDE);
#pragma unroll
  for (int q=0;q<8;q++){ ulonglong2 v = src[q]; dst[2*q]=v.x; dst[2*q+1]=v.y; }
}

__global__ void __launch_bounds__(128, 2)
rssm_kernel(const float* __restrict__ s0, const float* __restrict__ h0,
            const float* __restrict__ actions,
            const float* __restrict__ W_ih, const float* __restrict__ W_hh,
            const float* __restrict__ b_ih, const float* __restrict__ b_hh,
            const float* __restrict__ fc1_w, const float* __restrict__ fc1_b,
            const float* __restrict__ mean_w, const float* __restrict__ mean_b,
            const float* __restrict__ std_w, const float* __restrict__ std_b,
            float* __restrict__ out, int B, int T, int n_steps)
{
  __shared__ __align__(16) float sw[W_FLOATS];
  __shared__ __align__(16) ull  xbuf[BUF_ULL];
  const int tid  = threadIdx.x;
  const int w    = tid >> 5;                 // warp id 0..3 -> rows 8w..8w+7
  const int lane = tid & 31;
  const int eA   = lane;                     // element indices within CTA
  const int eB   = lane + 32;
  const int gA   = blockIdx.x*64 + eA;       // global elements
  const int gB   = blockIdx.x*64 + eB;

  // ---- stage weights ----
  for (int i=tid;i<W_FLOATS;i+=128) sw[i]=0.0f;
  __syncthreads();
  for (int i=tid;i<32*32;i+=128){ int j=i>>5,k=i&31; sw[j*NH_ROW+k]=W_hh[i]; }
  for (int i=tid;i<32*40;i+=128){ int j=i/40,k=i-j*40; sw[j*NH_ROW+34+k]=W_ih[i]; }
  for (int i=tid;i<32*32;i+=128){
    int j=i>>5,k=i&31;
    sw[FC1_OFF + j*M_ROW+k]=fc1_w[i];
    sw[MEAN_OFF+ j*M_ROW+k]=mean_w[i];
    sw[STD_OFF + j*M_ROW+k]=std_w[i];
  }
  if (tid < 32){
    int j=tid;
    sw[j*NH_ROW+32]          = b_ih[j]+b_hh[j];
    sw[FC1_OFF + j*M_ROW+32] = fc1_b[j];
    sw[MEAN_OFF+ j*M_ROW+32] = mean_b[j];
    sw[STD_OFF + j*M_ROW+32] = std_b[j];
  }

  // seed SLOT_S with s0 (threads 0..63 -> elements 0..63)
  if (tid < 64){
    const float4* s4 = (const float4*)(s0 + (size_t)(blockIdx.x*64 + tid)*32);
    ulonglong2* dst = (ulonglong2*)(xbuf + SLOT_S*BUF_SLOT + tid*BUF_STRIDE);
#pragma unroll
    for (int q=0;q<8;q++){ F4U t; t.f=s4[q]; ulonglong2 v; v.x=t.u.x; v.y=t.u.y; dst[q]=v; }
  }
  __syncthreads();

  const float* nhb = sw + (w*8)*NH_ROW;
  const float* f1b = sw + FC1_OFF  + (w*8)*M_ROW;
  const float* mnb = sw + MEAN_OFF + (w*8)*M_ROW;
  const float* sdb = sw + STD_OFF  + (w*8)*M_ROW;

  const ull ONE = pack2(1.0f, 0.0f);

  // per-element state in registers
  ull hA[16], hB[16], aA[4], aB[4];
  {
    const float4* h4A = (const float4*)(h0 + (size_t)gA*32);
    const float4* h4B = (const float4*)(h0 + (size_t)gB*32);
#pragma unroll
    for (int q=0;q<8;q++){
      F4U tA; tA.f=h4A[q]; hA[2*q]=tA.u.x; hA[2*q+1]=tA.u.y;
      F4U tB; tB.f=h4B[q]; hB[2*q]=tB.u.x; hB[2*q+1]=tB.u.y;
    }
    const float4* a4A=(const float4*)(actions + (size_t)gA*T*8);
    const float4* a4B=(const float4*)(actions + (size_t)gB*T*8);
    F4U x0,x1,y0,y1; x0.f=a4A[0]; x1.f=a4A[1]; y0.f=a4B[0]; y1.f=a4B[1];
    aA[0]=x0.u.x; aA[1]=x0.u.y; aA[2]=x1.u.x; aA[3]=x1.u.y;
    aB[0]=y0.u.x; aB[1]=y0.u.y; aB[2]=y1.u.x; aB[3]=y1.u.y;
  }

  for (int t=0;t<n_steps;t++){
    // prefetch next step's actions
    F4U nA0,nA1,nB0,nB1;
    nA0.u.x=0ull; nA0.u.y=0ull; nA1.u.x=0ull; nA1.u.y=0ull;
    nB0.u.x=0ull; nB0.u.y=0ull; nB1.u.x=0ull; nB1.u.y=0ull;
    if (t+1<n_steps){
      const float4* a4A=(const float4*)(actions + ((size_t)gA*T + t+1)*8);
      const float4* a4B=(const float4*)(actions + ((size_t)gB*T + t+1)*8);
      nA0.f=a4A[0]; nA1.f=a4A[1]; nB0.f=a4B[0]; nB1.f=a4B[1];
    }

    // ---- s from SLOT_S ----
    ull sA[16], sB[16];
    get16(xbuf, SLOT_S, eA, sA);
    get16(xbuf, SLOT_S, eB, sB);

    // ---- h_t = tanh(NH @ [h,1,s,a]) ----
    float yA[8], yB[8];
    dotNH2(nhb, hA, hB, sA, sB, aA, aB, ONE, yA, yB);
#pragma unroll
    for (int i=0;i<8;i++){ yA[i]=tanh_approx(yA[i]); yB[i]=tanh_approx(yB[i]); }
    put8(xbuf, SLOT_H, eA, w, yA);
    put8(xbuf, SLOT_H, eB, w, yB);
    __syncthreads();
    get16(xbuf, SLOT_H, eA, hA);
    get16(xbuf, SLOT_H, eB, hB);

    // ---- hid = elu(FC1 @ [h,1]) ----
    dotM2(f1b, hA, hB, ONE, yA, yB);
#pragma unroll
    for (int i=0;i<8;i++){
      float x=yA[i]; yA[i]= x>0.0f ? x : (__expf(x)-1.0f);
      float z=yB[i]; yB[i]= z>0.0f ? z : (__expf(z)-1.0f);
    }
    put8(xbuf, SLOT_HID, eA, w, yA);
    put8(xbuf, SLOT_HID, eB, w, yB);
    __syncthreads();
    ull uA[16], uB[16];
    get16(xbuf, SLOT_HID, eA, uA);
    get16(xbuf, SLOT_HID, eB, uB);

    // ---- mean = MEAN @ [hid,1]  (also next-step s) ----
    dotM2(mnb, uA, uB, ONE, yA, yB);
    put8(xbuf, SLOT_S, eA, w, yA);
    put8(xbuf, SLOT_S, eB, w, yB);

    float* orowA = out + ((size_t)t*B + gA)*64 + w*8;
    float* orowB = out + ((size_t)t*B + gB)*64 + w*8;
    {
      float4 f0,f1,g0,g1;
      f0.x=yA[0]; f0.y=yA[1]; f0.z=yA[2]; f0.w=yA[3];
      f1.x=yA[4]; f1.y=yA[5]; f1.z=yA[6]; f1.w=yA[7];
      g0.x=yB[0]; g0.y=yB[1]; g0.z=yB[2]; g0.w=yB[3];
      g1.x=yB[4]; g1.y=yB[5]; g1.z=yB[6]; g1.w=yB[7];
      ((float4*)orowA)[0]=f0; ((float4*)orowA)[1]=f1;
      ((float4*)orowB)[0]=g0; ((float4*)orowB)[1]=g1;
    }

    // ---- std = softplus(STD @ [hid,1]) + 1e-5 ----
    dotM2(sdb, uA, uB, ONE, yA, yB);
#pragma unroll
    for (int i=0;i<8;i++){
      yA[i]=softplus_fast(yA[i])+1e-5f;
      yB[i]=softplus_fast(yB[i])+1e-5f;
    }
    {
      float4 f0,f1,g0,g1;
      f0.x=yA[0]; f0.y=yA[1]; f0.z=yA[2]; f0.w=yA[3];
      f1.x=yA[4]; f1.y=yA[5]; f1.z=yA[6]; f1.w=yA[7];
      g0.x=yB[0]; g0.y=yB[1]; g0.z=yB[2]; g0.w=yB[3];
      g1.x=yB[4]; g1.y=yB[5]; g1.z=yB[6]; g1.w=yB[7];
      ((float4*)(orowA+32))[0]=f0; ((float4*)(orowA+32))[1]=f1;
      ((float4*)(orowB+32))[0]=g0; ((float4*)(orowB+32))[1]=g1;
    }

    // commit prefetched actions; fence SLOT_S write -> next-step read
    aA[0]=nA0.u.x; aA[1]=nA0.u.y; aA[2]=nA1.u.x; aA[3]=nA1.u.y;
    aB[0]=nB0.u.x; aB[1]=nB0.u.y; aB[2]=nB1.u.x; aB[3]=nB1.u.y;
    __syncthreads();
  }
}

extern "C" void kernel_launch(void* const* d_in, const int* in_sizes, int n_in,
                              void* d_out, int out_size) {
  const float* s0      = (const float*)d_in[0];
  const float* h0      = (const float*)d_in[1];
  const float* actions = (const float*)d_in[2];
  const float* W_ih    = (const float*)d_in[3];
  const float* W_hh    = (const float*)d_in[4];
  const float* b_ih    = (const float*)d_in[5];
  const float* b_hh    = (const float*)d_in[6];
  const float* fc1_w   = (const float*)d_in[7];
  const float* fc1_b   = (const float*)d_in[8];
  const float* mean_w  = (const float*)d_in[9];
  const float* mean_b  = (const float*)d_in[10];
  const float* std_w   = (const float*)d_in[11];
  const float* std_b   = (const float*)d_in[12];
  float* out = (float*)d_out;

  int B = in_sizes[0] / 32;                 // s0 is [B, 32]
  int T = in_sizes[2] / (B * 8);            // actions is [B, T, 8]
  int n_steps = out_size / (B * 64);        // out is [n_steps, B, 64]
  if (n_steps > T) n_steps = T;

  cudaFuncSetAttribute(rssm_kernel, cudaFuncAttributePreferredSharedMemoryCarveout, 100);

  rssm_kernel<<<B/64, 128>>>(s0, h0, actions, W_ih, W_hh, b_ih, b_hh,
                             fc1_w, fc1_b, mean_w, mean_b, std_w, std_b,
                             out, B, T, n_steps);
}